// round 16
// baseline (speedup 1.0000x reference)
#include <cuda_runtime.h>
#include <cstdint>

#define Hh 512
#define Ww 512
#define NT 256            /* threads; each owns 2 adjacent output columns     */
#define TH 67             /* output rows per block; 67+10 = 77 = 7*11         */
#define NCH 7             /* chunks of 11 rows                                */
#define ROWB 2048         /* bytes per smem row = full 512-float circle      */
#define CHB (11 * ROWB)   /* 22528 bytes per chunk buffer                     */

typedef unsigned long long pk_t;   /* {lo=col c, hi=col c+1} f32x2 */

__device__ __forceinline__ pk_t pk2(float a, float b) {
    pk_t r; asm("mov.b64 %0, {%1, %2};" : "=l"(r) : "f"(a), "f"(b)); return r;
}
__device__ __forceinline__ void punpack(pk_t a, float& lo, float& hi) {
    asm("mov.b64 {%0, %1}, %2;" : "=f"(lo), "=f"(hi) : "l"(a));
}
__device__ __forceinline__ pk_t padd(pk_t a, pk_t b) {
    pk_t r; asm("add.rn.f32x2 %0, %1, %2;" : "=l"(r) : "l"(a), "l"(b)); return r;
}
__device__ __forceinline__ pk_t pmul(pk_t a, pk_t b) {
    pk_t r; asm("mul.rn.f32x2 %0, %1, %2;" : "=l"(r) : "l"(a), "l"(b)); return r;
}
__device__ __forceinline__ pk_t pfma(pk_t a, pk_t b, pk_t c) {
    pk_t r; asm("fma.rn.f32x2 %0, %1, %2, %3;" : "=l"(r) : "l"(a), "l"(b), "l"(c)); return r;
}
__device__ __forceinline__ pk_t ldsp(uint32_t addr) {
    pk_t v; asm volatile("ld.shared.u64 %0, [%1];" : "=l"(v) : "r"(addr)); return v;
}
__device__ __forceinline__ float ldsf(uint32_t addr) {
    float f; asm volatile("ld.shared.f32 %0, [%1];" : "=f"(f) : "r"(addr)); return f;
}

__device__ __forceinline__ void mbar_init(uint32_t mb, uint32_t cnt) {
    asm volatile("mbarrier.init.shared.b64 [%0], %1;" :: "r"(mb), "r"(cnt) : "memory");
}
__device__ __forceinline__ void mbar_expect_tx(uint32_t mb, uint32_t bytes) {
    asm volatile("mbarrier.arrive.expect_tx.shared.b64 _, [%0], %1;" :: "r"(mb), "r"(bytes) : "memory");
}
__device__ __forceinline__ void mbar_wait(uint32_t mb, uint32_t parity) {
    uint32_t done;
    asm volatile("{\n\t.reg .pred p;\n\t"
                 "mbarrier.try_wait.parity.acquire.cta.shared::cta.b64 p, [%1], %2;\n\t"
                 "selp.b32 %0, 1, 0, p;\n\t}"
                 : "=r"(done) : "r"(mb), "r"(parity) : "memory");
    if (!done) {
        asm volatile("{\n\t.reg .pred P1;\n\t"
                     "W_%=:\n\t"
                     "mbarrier.try_wait.parity.acquire.cta.shared::cta.b64 P1, [%0], %1, 0x989680;\n\t"
                     "@P1 bra.uni D_%=;\n\t"
                     "bra.uni W_%=;\n\t"
                     "D_%=:\n\t}"
                     :: "r"(mb), "r"(parity) : "memory");
    }
}
__device__ __forceinline__ void bulk_cp(uint32_t dst, const float* src, uint32_t bytes, uint32_t mb) {
    asm volatile("cp.async.bulk.shared::cta.global.mbarrier::complete_tx::bytes [%0], [%1], %2, [%3];"
                 :: "r"(dst), "l"(src), "r"(bytes), "r"(mb) : "memory");
}

// out[b,i,j] = sum_{1<=|a|+|c|<=5} w_{|a|+|c|} * s[b,(i+a)%512,(j+c)%512]
// Per input row: R_t[j] = x[j-t]+x[j+t]; F_m = sum_t W(m+t) R_t; row r feeds out rows r±m.
// 2 columns per thread, 256 threads = full 512-col rows (no halo, no wrap-split fill).
// 11 cyclic f32x2 accumulators w/ drained-slot assignment; double-buffered
// cp.async.bulk 11-row chunks (one 2048B copy per row, issued by tid 0).
// __launch_bounds__(256,3): 85-reg budget >> natural 72 regs (NO remat, unlike R13's
// 64-reg squeeze) -> 3 blocks x 8 warps = 24 warps/SM.
__global__ __launch_bounds__(NT, 3)
void lc_kernel(const float* __restrict__ in, const float* __restrict__ w,
               float* __restrict__ out)
{
    extern __shared__ float sh[];                    // 2 * CHB bytes
    __shared__ unsigned long long mbar[2];

    const int tid = threadIdx.x;
    const int i0  = blockIdx.x * TH;
    const float* g = in  + (size_t)blockIdx.y * (Hh * Ww);
    float*       o = out + (size_t)blockIdx.y * (Hh * Ww);

    uint32_t sbase, mb0;
    asm("{ .reg .u64 t; cvta.to.shared.u64 t, %1; cvt.u32.u64 %0, t; }" : "=r"(sbase) : "l"(sh));
    asm("{ .reg .u64 t; cvta.to.shared.u64 t, %1; cvt.u32.u64 %0, t; }" : "=r"(mb0) : "l"(&mbar[0]));

    if (tid == 0) {
        mbar_init(mb0, 1);
        mbar_init(mb0 + 8, 1);
        asm volatile("fence.proxy.async.shared::cta;" ::: "memory");
    }
    __syncthreads();

    auto issue = [&](int c) {
        if (tid == 0) {
            const uint32_t mb  = mb0 + (c & 1) * 8;
            uint32_t dst = sbase + (c & 1) * CHB;
            mbar_expect_tx(mb, CHB);
            const int base_r = i0 - 5 + c * 11;
#pragma unroll
            for (int r = 0; r < 11; r++) {
                const int gr = (base_r + r) & (Hh - 1);
                bulk_cp(dst, g + gr * Ww, ROWB, mb);
                dst += ROWB;
            }
        }
    };

    issue(0);
    issue(1);

    const pk_t w1 = pk2(w[0], w[0]);
    const pk_t w2 = pk2(w[1], w[1]);
    const pk_t w3 = pk2(w[2], w[2]);
    const pk_t w4 = pk2(w[3], w[3]);
    const pk_t w5 = pk2(w[4], w[4]);
    const pk_t zz = pk2(0.0f, 0.0f);

    // per-thread wrapped byte offsets within a 512-float row (base col c0 = 2*tid)
    const int c0 = 2 * tid;
    const uint32_t ob_m2 = (uint32_t)(((c0 - 4) & (Ww - 1)) * 4);   // {c-4,c-3}
    const uint32_t ob_m1 = (uint32_t)(((c0 - 2) & (Ww - 1)) * 4);   // {c-2,c-1}
    const uint32_t ob_0  = (uint32_t)(c0 * 4);                      // {c,  c+1}
    const uint32_t ob_1  = (uint32_t)(((c0 + 2) & (Ww - 1)) * 4);   // {c+2,c+3}
    const uint32_t ob_2  = (uint32_t)(((c0 + 4) & (Ww - 1)) * 4);   // {c+4,c+5}
    const uint32_t ob_m5 = (uint32_t)(((c0 - 5) & (Ww - 1)) * 4);   // x[c-5]
    const uint32_t ob_p6 = (uint32_t)(((c0 + 6) & (Ww - 1)) * 4);   // x[c+6]

    pk_t acc[11];
#pragma unroll
    for (int s = 0; s < 11; s++) acc[s] = zz;

    for (int c = 0; c < NCH; c++) {
        mbar_wait(mb0 + (c & 1) * 8, (c >> 1) & 1);

        const uint32_t buf = sbase + (c & 1) * CHB;
        const uint32_t am2 = buf + ob_m2;
        const uint32_t am1 = buf + ob_m1;
        const uint32_t a0  = buf + ob_0;
        const uint32_t a1  = buf + ob_1;
        const uint32_t a2  = buf + ob_2;
        const uint32_t am5 = buf + ob_m5;
        const uint32_t ap6 = buf + ob_p6;

#pragma unroll
        for (int u = 0; u < 11; u++) {
            const uint32_t off = u * ROWB;
            pk_t Dm2 = ldsp(am2 + off);
            pk_t Dm1 = ldsp(am1 + off);
            pk_t D0  = ldsp(a0  + off);
            pk_t D1  = ldsp(a1  + off);
            pk_t D2  = ldsp(a2  + off);
            float xm5 = ldsf(am5 + off);
            float xp6 = ldsf(ap6 + off);

            float dm2l, dm2h, dm1l, dm1h, d0l, d0h, d1l, d1h, d2l, d2h;
            punpack(Dm2, dm2l, dm2h);
            punpack(Dm1, dm1l, dm1h);
            punpack(D0,  d0l,  d0h);
            punpack(D1,  d1l,  d1h);
            punpack(D2,  d2l,  d2h);

            pk_t R0 = D0;
            pk_t R2 = padd(Dm1, D1);
            pk_t R4 = padd(Dm2, D2);
            pk_t R1 = pk2(dm1h + d0h, d0l + d1l);
            pk_t R3 = pk2(dm2h + d1h, dm1l + d2l);
            pk_t R5 = pk2(xm5  + d2h, dm2l + xp6);

            pk_t F0 = pfma(w5, R5, pfma(w4, R4, pfma(w3, R3, pfma(w2, R2, pmul(w1, R1)))));
            pk_t F1 = pfma(w5, R4, pfma(w4, R3, pfma(w3, R2, pfma(w2, R1, pmul(w1, R0)))));
            pk_t F2 = pfma(w5, R3, pfma(w4, R2, pfma(w3, R1, pmul(w2, R0))));
            pk_t F3 = pfma(w5, R2, pfma(w4, R1, pmul(w3, R0)));
            pk_t F4 = pfma(w5, R1, pmul(w4, R0));
            pk_t F5 = pmul(w5, R0);

            acc[(u + 5)  % 11] = padd(acc[(u + 5)  % 11], F0);
            acc[(u + 6)  % 11] = padd(acc[(u + 6)  % 11], F1);
            acc[(u + 4)  % 11] = padd(acc[(u + 4)  % 11], F1);
            acc[(u + 7)  % 11] = padd(acc[(u + 7)  % 11], F2);
            acc[(u + 3)  % 11] = padd(acc[(u + 3)  % 11], F2);
            acc[(u + 8)  % 11] = padd(acc[(u + 8)  % 11], F3);
            acc[(u + 2)  % 11] = padd(acc[(u + 2)  % 11], F3);
            acc[(u + 9)  % 11] = padd(acc[(u + 9)  % 11], F4);
            acc[(u + 1)  % 11] = padd(acc[(u + 1)  % 11], F4);
            acc[(u + 10) % 11] = F5;                 // slot drained last iter: assign
            acc[u]             = padd(acc[u],        F5);

            const int k = c * 11 + u;
            if (k >= 10) {
                const int orow = i0 + k - 10;
                if (orow < Hh) {
                    *(pk_t*)(o + orow * Ww + c0) = acc[u];   // STG.64
                }
            }
            // no reset: next write to acc[u] is the assignment at iter u+1
        }

        __syncthreads();                 // all lanes done reading buf (c&1)
        if (c + 2 < NCH) issue(c + 2);   // refill for chunk c+2
    }
}

extern "C" void kernel_launch(void* const* d_in, const int* in_sizes, int n_in,
                              void* d_out, int out_size)
{
    int gi = 0, wi = 1;
    if (in_sizes[0] == 5) { gi = 1; wi = 0; }
    const float* in = (const float*)d_in[gi];
    const float* w  = (const float*)d_in[wi];
    float* out = (float*)d_out;

    int B = in_sizes[gi] / (Hh * Ww);                 // 64
    size_t smem = (size_t)2 * CHB;                    // 45056 B

    static int attr_set = 0;
    if (!attr_set) {
        cudaFuncSetAttribute(lc_kernel, cudaFuncAttributeMaxDynamicSharedMemorySize, (int)smem);
        // NOTE: do NOT touch PreferredSharedMemoryCarveout — measured 60% regression (R7).
        attr_set = 1;
    }

    dim3 grid((Hh + TH - 1) / TH, B);                 // 8 x 64 = 512 blocks
    lc_kernel<<<grid, NT, smem>>>(in, w, out);
}

// round 17
// speedup vs baseline: 1.0553x; 1.0553x over previous
#include <cuda_runtime.h>
#include <cstdint>

#define Hh 512
#define Ww 512
#define NT 128            /* threads; each owns 2 adjacent output columns     */
#define TWC 256           /* output columns per block                         */
#define TH 67             /* output rows per block; 67+10 = 77 = 7*11         */
#define NCH 7             /* chunks of 11 rows                                */
#define NBUF 3            /* triple buffer                                    */
#define SROWF 272         /* smem row width in floats: cols [j0-8, j0+264)    */
#define ROWB (SROWF * 4)  /* 1088 bytes per smem row                          */
#define CHB (11 * ROWB)   /* 11968 bytes per chunk buffer                     */

typedef unsigned long long pk_t;   /* {lo=col c, hi=col c+1} f32x2 */

__device__ __forceinline__ pk_t pk2(float a, float b) {
    pk_t r; asm("mov.b64 %0, {%1, %2};" : "=l"(r) : "f"(a), "f"(b)); return r;
}
__device__ __forceinline__ void punpack(pk_t a, float& lo, float& hi) {
    asm("mov.b64 {%0, %1}, %2;" : "=f"(lo), "=f"(hi) : "l"(a));
}
__device__ __forceinline__ pk_t padd(pk_t a, pk_t b) {
    pk_t r; asm("add.rn.f32x2 %0, %1, %2;" : "=l"(r) : "l"(a), "l"(b)); return r;
}
__device__ __forceinline__ pk_t pmul(pk_t a, pk_t b) {
    pk_t r; asm("mul.rn.f32x2 %0, %1, %2;" : "=l"(r) : "l"(a), "l"(b)); return r;
}
__device__ __forceinline__ pk_t pfma(pk_t a, pk_t b, pk_t c) {
    pk_t r; asm("fma.rn.f32x2 %0, %1, %2, %3;" : "=l"(r) : "l"(a), "l"(b), "l"(c)); return r;
}

__device__ __forceinline__ void mbar_init(uint32_t mb, uint32_t cnt) {
    asm volatile("mbarrier.init.shared.b64 [%0], %1;" :: "r"(mb), "r"(cnt) : "memory");
}
__device__ __forceinline__ void mbar_expect_tx(uint32_t mb, uint32_t bytes) {
    asm volatile("mbarrier.arrive.expect_tx.shared.b64 _, [%0], %1;" :: "r"(mb), "r"(bytes) : "memory");
}
__device__ __forceinline__ void mbar_wait(uint32_t mb, uint32_t parity) {
    uint32_t done;
    asm volatile("{\n\t.reg .pred p;\n\t"
                 "mbarrier.try_wait.parity.acquire.cta.shared::cta.b64 p, [%1], %2;\n\t"
                 "selp.b32 %0, 1, 0, p;\n\t}"
                 : "=r"(done) : "r"(mb), "r"(parity) : "memory");
    if (!done) {
        asm volatile("{\n\t.reg .pred P1;\n\t"
                     "W_%=:\n\t"
                     "mbarrier.try_wait.parity.acquire.cta.shared::cta.b64 P1, [%0], %1, 0x989680;\n\t"
                     "@P1 bra.uni D_%=;\n\t"
                     "bra.uni W_%=;\n\t"
                     "D_%=:\n\t}"
                     :: "r"(mb), "r"(parity) : "memory");
    }
}
__device__ __forceinline__ void bulk_cp(uint32_t dst, const float* src, uint32_t bytes, uint32_t mb) {
    asm volatile("cp.async.bulk.shared::cta.global.mbarrier::complete_tx::bytes [%0], [%1], %2, [%3];"
                 :: "r"(dst), "l"(src), "r"(bytes), "r"(mb) : "memory");
}

// out[b,i,j] = sum_{1<=|a|+|c|<=5} w_{|a|+|c|} * s[b,(i+a)%512,(j+c)%512]
// Per input row: R_t[j] = x[j-t]+x[j+t]; F_m = sum_t W(m+t) R_t; row r feeds out rows r±m.
// 11 cyclic f32x2 accumulators (2 adjacent columns packed per thread), drained-slot
// assignment. Rows stream via TRIPLE-buffered cp.async.bulk 11-row chunks: fills get a
// 3-chunk lead, and the buffer-protection __syncthreads exists ONLY before a refill,
// so the last NBUF chunks run sync-free (warps retire staggered, no tail convoy).
__global__ __launch_bounds__(NT, 7)
void lc_kernel(const float* __restrict__ in, const float* __restrict__ w,
               float* __restrict__ out)
{
    extern __shared__ float sh[];                    // NBUF * CHB bytes
    __shared__ unsigned long long mbar[NBUF];

    const int tid = threadIdx.x;
    const int j0  = blockIdx.x * TWC;                // 0 or 256
    const int i0  = blockIdx.y * TH;
    const float* g = in  + (size_t)blockIdx.z * (Hh * Ww);
    float*       o = out + (size_t)blockIdx.z * (Hh * Ww);

    uint32_t sbase, mb0;
    asm("{ .reg .u64 t; cvta.to.shared.u64 t, %1; cvt.u32.u64 %0, t; }" : "=r"(sbase) : "l"(sh));
    asm("{ .reg .u64 t; cvta.to.shared.u64 t, %1; cvt.u32.u64 %0, t; }" : "=r"(mb0) : "l"(&mbar[0]));

    if (tid == 0) {
        mbar_init(mb0,      1);
        mbar_init(mb0 + 8,  1);
        mbar_init(mb0 + 16, 1);
        asm volatile("fence.proxy.async.shared::cta;" ::: "memory");
    }
    __syncthreads();

    // fill window = global cols [j0-8, j0+264) mod 512; wrap split
    const int ws = (j0 - 8) & (Ww - 1);              // 504 or 248 (mult of 4)
    const int n1 = Ww - ws;                          // floats before wrap: 8 or 264
    const uint32_t b1 = (uint32_t)(n1 * 4);          // 32 or 1056 (16B multiples)

    auto issue = [&](int c) {
        if (tid == 0) {
            const int bufi = c % NBUF;
            const uint32_t mb  = mb0 + bufi * 8;
            uint32_t dst = sbase + bufi * CHB;
            mbar_expect_tx(mb, CHB);
            const int base_r = i0 - 5 + c * 11;
#pragma unroll
            for (int r = 0; r < 11; r++) {
                const int gr = (base_r + r) & (Hh - 1);
                const float* rowg = g + gr * Ww;
                bulk_cp(dst,      rowg + ws, b1,        mb);
                bulk_cp(dst + b1, rowg,      ROWB - b1, mb);
                dst += ROWB;
            }
        }
    };

    issue(0);
    issue(1);
    issue(2);

    const pk_t w1 = pk2(w[0], w[0]);
    const pk_t w2 = pk2(w[1], w[1]);
    const pk_t w3 = pk2(w[2], w[2]);
    const pk_t w4 = pk2(w[3], w[3]);
    const pk_t w5 = pk2(w[4], w[4]);
    const pk_t zz = pk2(0.0f, 0.0f);

    // per-thread smem byte offsets within a row (global col j0+x -> float idx x+8)
    const int t2 = 2 * tid;
    const uint32_t ob_m2 = (uint32_t)((t2 + 4)  * 4);   // {c-4,c-3}
    const uint32_t ob_m1 = (uint32_t)((t2 + 6)  * 4);   // {c-2,c-1}
    const uint32_t ob_0  = (uint32_t)((t2 + 8)  * 4);   // {c,  c+1}
    const uint32_t ob_1  = (uint32_t)((t2 + 10) * 4);   // {c+2,c+3}
    const uint32_t ob_2  = (uint32_t)((t2 + 12) * 4);   // {c+4,c+5}
    const uint32_t ob_lo = (uint32_t)((t2 + 3)  * 4);   // x[c-5]
    const uint32_t ob_hi = (uint32_t)((t2 + 14) * 4);   // x[c+6]

    pk_t acc[11];
#pragma unroll
    for (int s = 0; s < 11; s++) acc[s] = zz;

    const char* shc = (const char*)sh;

    for (int c = 0; c < NCH; c++) {
        const int bufi = c % NBUF;
        mbar_wait(mb0 + bufi * 8, (c / NBUF) & 1);

        const char* buf = shc + bufi * CHB;
        const char* p_m2 = buf + ob_m2;
        const char* p_m1 = buf + ob_m1;
        const char* p_0  = buf + ob_0;
        const char* p_1  = buf + ob_1;
        const char* p_2  = buf + ob_2;
        const char* p_lo = buf + ob_lo;
        const char* p_hi = buf + ob_hi;

#pragma unroll
        for (int u = 0; u < 11; u++) {
            const int off = u * ROWB;
            pk_t Dm2 = *(const pk_t*)(p_m2 + off);
            pk_t Dm1 = *(const pk_t*)(p_m1 + off);
            pk_t D0  = *(const pk_t*)(p_0  + off);
            pk_t D1  = *(const pk_t*)(p_1  + off);
            pk_t D2  = *(const pk_t*)(p_2  + off);
            float xm5 = *(const float*)(p_lo + off);
            float xp6 = *(const float*)(p_hi + off);

            float dm2l, dm2h, dm1l, dm1h, d0l, d0h, d1l, d1h, d2l, d2h;
            punpack(Dm2, dm2l, dm2h);
            punpack(Dm1, dm1l, dm1h);
            punpack(D0,  d0l,  d0h);
            punpack(D1,  d1l,  d1h);
            punpack(D2,  d2l,  d2h);

            pk_t R0 = D0;
            pk_t R2 = padd(Dm1, D1);
            pk_t R4 = padd(Dm2, D2);
            pk_t R1 = pk2(dm1h + d0h, d0l + d1l);
            pk_t R3 = pk2(dm2h + d1h, dm1l + d2l);
            pk_t R5 = pk2(xm5  + d2h, dm2l + xp6);

            pk_t F0 = pfma(w5, R5, pfma(w4, R4, pfma(w3, R3, pfma(w2, R2, pmul(w1, R1)))));
            pk_t F1 = pfma(w5, R4, pfma(w4, R3, pfma(w3, R2, pfma(w2, R1, pmul(w1, R0)))));
            pk_t F2 = pfma(w5, R3, pfma(w4, R2, pfma(w3, R1, pmul(w2, R0))));
            pk_t F3 = pfma(w5, R2, pfma(w4, R1, pmul(w3, R0)));
            pk_t F4 = pfma(w5, R1, pmul(w4, R0));
            pk_t F5 = pmul(w5, R0);

            acc[(u + 5)  % 11] = padd(acc[(u + 5)  % 11], F0);
            acc[(u + 6)  % 11] = padd(acc[(u + 6)  % 11], F1);
            acc[(u + 4)  % 11] = padd(acc[(u + 4)  % 11], F1);
            acc[(u + 7)  % 11] = padd(acc[(u + 7)  % 11], F2);
            acc[(u + 3)  % 11] = padd(acc[(u + 3)  % 11], F2);
            acc[(u + 8)  % 11] = padd(acc[(u + 8)  % 11], F3);
            acc[(u + 2)  % 11] = padd(acc[(u + 2)  % 11], F3);
            acc[(u + 9)  % 11] = padd(acc[(u + 9)  % 11], F4);
            acc[(u + 1)  % 11] = padd(acc[(u + 1)  % 11], F4);
            acc[(u + 10) % 11] = F5;                 // slot drained last iter: assign
            acc[u]             = padd(acc[u],        F5);

            const int k = c * 11 + u;
            if (k >= 10) {
                const int orow = i0 + k - 10;
                if (orow < Hh) {
                    *(pk_t*)(o + orow * Ww + j0 + t2) = acc[u];   // STG.64
                }
            }
            // no reset: next write to acc[u] is the assignment at iter u+1
        }

        if (c + NBUF < NCH) {
            __syncthreads();        // only needed to protect buffer reuse
            issue(c + NBUF);        // refill bufi for chunk c+NBUF
        }
        // chunks NCH-NBUF..NCH-1: no refill -> no sync -> staggered retirement
    }
}

extern "C" void kernel_launch(void* const* d_in, const int* in_sizes, int n_in,
                              void* d_out, int out_size)
{
    int gi = 0, wi = 1;
    if (in_sizes[0] == 5) { gi = 1; wi = 0; }
    const float* in = (const float*)d_in[gi];
    const float* w  = (const float*)d_in[wi];
    float* out = (float*)d_out;

    int B = in_sizes[gi] / (Hh * Ww);                 // 64
    size_t smem = (size_t)NBUF * CHB;                 // 35904 B

    static int attr_set = 0;
    if (!attr_set) {
        cudaFuncSetAttribute(lc_kernel, cudaFuncAttributeMaxDynamicSharedMemorySize, (int)smem);
        // NOTE: do NOT touch PreferredSharedMemoryCarveout — measured 60% regression (R7).
        attr_set = 1;
    }

    dim3 grid(Ww / TWC, (Hh + TH - 1) / TH, B);       // 2 x 8 x 64 = 1024 blocks
    lc_kernel<<<grid, NT, smem>>>(in, w, out);
}